// round 9
// baseline (speedup 1.0000x reference)
#include <cuda_runtime.h>
#include <cstdint>

// Problem constants
#define Bn 16384
#define Fn 512
#define Pn 128
#define Cn 10

// Tiling
#define BM 32                 // rows per block
#define BK 32                 // K tile
#define NT 256                // threads (8 warps: 1M x 8N)
#define NTILE (Fn / BK)       // 16
#define A_SZ (32 * 144)       // 4608 bytes A region
#define STG_B (A_SZ + 128 * 144)   // 23040 bytes per stage
#define OFF_TAIL (2 * STG_B)       // 46080
#define SROW 132              // si row stride (words)
#define UW 16                 // u_t row stride (words)
#define SMEM_BYTES (OFF_TAIL + (32 + 128 + 128 * UW + 128 + 128) * 4)   // 55936

__device__ __forceinline__ uint32_t cvta_s(const void* p) {
    return (uint32_t)__cvta_generic_to_shared(p);
}
__device__ __forceinline__ void cp16(uint32_t dst, const void* src) {
    asm volatile("cp.async.ca.shared.global [%0], [%1], 16;" :: "r"(dst), "l"(src));
}
template <int N>
__device__ __forceinline__ void cp_wait() {
    asm volatile("cp.async.wait_group %0;" :: "n"(N) : "memory");
}
__device__ __forceinline__ void ldsm4(uint32_t* r, uint32_t addr) {
    asm volatile("ldmatrix.sync.aligned.m8n8.x4.shared.b16 {%0,%1,%2,%3}, [%4];"
        : "=r"(r[0]), "=r"(r[1]), "=r"(r[2]), "=r"(r[3]) : "r"(addr));
}
#define MMA_TF32(cc, a0, a1, a2, a3, b0, b1)                                     \
    asm volatile(                                                                \
        "mma.sync.aligned.m16n8k8.row.col.f32.tf32.tf32.f32 "                    \
        "{%0,%1,%2,%3},{%4,%5,%6,%7},{%8,%9},{%0,%1,%2,%3};"                     \
        : "+f"((cc)[0]), "+f"((cc)[1]), "+f"((cc)[2]), "+f"((cc)[3])             \
        : "r"(a0), "r"(a1), "r"(a2), "r"(a3), "r"(b0), "r"(b1))

__global__ __launch_bounds__(NT, 4)
void ds_kernel(const float* __restrict__ x, const float* __restrict__ w,
               const float* __restrict__ eta, const float* __restrict__ xi,
               const float* __restrict__ beta, float* __restrict__ out)
{
    extern __shared__ char smem[];
    float* sit = (float*)smem;                      // [BM][SROW], aliases stages
    float* xsq = (float*)(smem + OFF_TAIL);         // [32]
    float* wsq = xsq + 32;                          // [128]
    float* u_t = wsq + 128;                         // [128][UW]
    float* alp = u_t + 128 * UW;                    // [128]
    float* gam = alp + 128;                         // [128]

    const int tid  = threadIdx.x;
    const int row0 = blockIdx.x * BM;
    const uint32_t sbase = cvta_s(smem);

    // ---- async copy: per thread per tile 1 A cp16 + 4 B cp16 ----
    const int oct = tid >> 3;     // 0..31 (row)
    const int q8  = tid & 7;      // float4 slot
    const float4* xg = (const float4*)x;   // 128 float4 per row
    const float4* wg = (const float4*)w;

#define COPY(t, stg)                                                              \
    do {                                                                          \
        const uint32_t base_ = sbase + (stg) * STG_B + oct * 144 + q8 * 16;       \
        cp16(base_, xg + (size_t)(row0 + oct) * 128 + (t) * 8 + q8);              \
        cp16(base_ + A_SZ, wg + (size_t)oct * 128 + (t) * 8 + q8);                \
        cp16(base_ + A_SZ + 32 * 144, wg + (size_t)(oct + 32) * 128 + (t) * 8 + q8); \
        cp16(base_ + A_SZ + 64 * 144, wg + (size_t)(oct + 64) * 128 + (t) * 8 + q8); \
        cp16(base_ + A_SZ + 96 * 144, wg + (size_t)(oct + 96) * 128 + (t) * 8 + q8); \
        asm volatile("cp.async.commit_group;" ::: "memory");                      \
    } while (0)

    COPY(0, 0);
    COPY(1, 1);

    // ---- per-prototype tables (overlapped with first copies) ----
    if (tid < Pn) {
        const int p = tid;
        float e = eta[p];
        gam[p] = e * e;
        alp[p] = 1.0f / (1.0f + __expf(-xi[p]));
        float b2[Cn];
        float bs = 0.0f;
        #pragma unroll
        for (int c = 0; c < Cn; c++) {
            float bv = beta[c * Pn + p];
            b2[c] = bv * bv;
            bs += b2[c];
        }
        float invb = 1.0f / bs;
        #pragma unroll
        for (int s = 0; s < UW; s++) u_t[p * UW + s] = 0.0f;
        #pragma unroll
        for (int c = 0; c < Cn; c++) {
            const int slot = (c < 9) ? (c / 3) * 4 + (c % 3) : 12;
            u_t[p * UW + slot] = b2[c] * invb;
        }
    }

    // ---- fragment addresses: warp tile 32(M) x 16(N) ----
    const int warp = tid >> 5, lane = tid & 31;
    const int n0 = warp * 16;                  // warp N base
    const int lr = lane >> 2, lc = lane & 3;

    const uint32_t aAddr0 = sbase + (lane & 15) * 144 + ((lane & 16) ? 16 : 0);
    const uint32_t aAddr1 = aAddr0 + 16 * 144;
    const uint32_t bAddr  = sbase + A_SZ
                          + (n0 + ((lane >> 4) & 1) * 8 + (lane & 7)) * 144
                          + ((lane & 8) ? 16 : 0);

    // sumsq readback offset (own stashed bytes, exact fp32 bits)
    const uint32_t sqOff = oct * 144 + q8 * 16;

    float acc[2][2][4];
    #pragma unroll
    for (int mi = 0; mi < 2; mi++)
        #pragma unroll
        for (int nj = 0; nj < 2; nj++)
            #pragma unroll
            for (int e = 0; e < 4; e++) acc[mi][nj][e] = 0.0f;

    float xacc = 0.0f, wa0 = 0.0f, wa1 = 0.0f, wa2 = 0.0f, wa3 = 0.0f;

    for (int t = 0; t < NTILE; t++) {
        const int stg = t & 1;
        if (t < NTILE - 1) cp_wait<1>();
        else               cp_wait<0>();
        __syncthreads();

        const char* sb = smem + stg * STG_B;
        // sumsq partials
        {
            float4 v = *(const float4*)(sb + sqOff);
            xacc += v.x * v.x + v.y * v.y + v.z * v.z + v.w * v.w;
            v = *(const float4*)(sb + A_SZ + sqOff);
            wa0 += v.x * v.x + v.y * v.y + v.z * v.z + v.w * v.w;
            v = *(const float4*)(sb + A_SZ + 32 * 144 + sqOff);
            wa1 += v.x * v.x + v.y * v.y + v.z * v.z + v.w * v.w;
            v = *(const float4*)(sb + A_SZ + 64 * 144 + sqOff);
            wa2 += v.x * v.x + v.y * v.y + v.z * v.z + v.w * v.w;
            v = *(const float4*)(sb + A_SZ + 96 * 144 + sqOff);
            wa3 += v.x * v.x + v.y * v.y + v.z * v.z + v.w * v.w;
        }

        const uint32_t so = stg * STG_B;
        #pragma unroll
        for (int k8 = 0; k8 < 4; k8++) {
            uint32_t a0[4], a1[4], b[4];
            ldsm4(a0, aAddr0 + so + k8 * 32);
            ldsm4(a1, aAddr1 + so + k8 * 32);
            ldsm4(b,  bAddr  + so + k8 * 32);
            MMA_TF32(acc[0][0], a0[0], a0[1], a0[2], a0[3], b[0], b[1]);
            MMA_TF32(acc[0][1], a0[0], a0[1], a0[2], a0[3], b[2], b[3]);
            MMA_TF32(acc[1][0], a1[0], a1[1], a1[2], a1[3], b[0], b[1]);
            MMA_TF32(acc[1][1], a1[0], a1[1], a1[2], a1[3], b[2], b[3]);
        }

        if (t + 2 < NTILE) {
            __syncthreads();          // all warps done reading stage stg
            COPY(t + 2, stg);
        }
    }

    // ---- reduce sumsq (8 threads per row) ----
    {
        float v = xacc;
        v += __shfl_xor_sync(0xffffffffu, v, 1);
        v += __shfl_xor_sync(0xffffffffu, v, 2);
        v += __shfl_xor_sync(0xffffffffu, v, 4);
        if (q8 == 0) xsq[oct] = v;
        float u0 = wa0, u1 = wa1, u2 = wa2, u3 = wa3;
        u0 += __shfl_xor_sync(0xffffffffu, u0, 1);
        u0 += __shfl_xor_sync(0xffffffffu, u0, 2);
        u0 += __shfl_xor_sync(0xffffffffu, u0, 4);
        u1 += __shfl_xor_sync(0xffffffffu, u1, 1);
        u1 += __shfl_xor_sync(0xffffffffu, u1, 2);
        u1 += __shfl_xor_sync(0xffffffffu, u1, 4);
        u2 += __shfl_xor_sync(0xffffffffu, u2, 1);
        u2 += __shfl_xor_sync(0xffffffffu, u2, 2);
        u2 += __shfl_xor_sync(0xffffffffu, u2, 4);
        u3 += __shfl_xor_sync(0xffffffffu, u3, 1);
        u3 += __shfl_xor_sync(0xffffffffu, u3, 2);
        u3 += __shfl_xor_sync(0xffffffffu, u3, 4);
        if (q8 == 0) {
            wsq[oct]      = u0;
            wsq[oct + 32] = u1;
            wsq[oct + 64] = u2;
            wsq[oct + 96] = u3;
        }
    }
    __syncthreads();   // fences last stage reads before sit aliases stages

    // ---- epilogue: si = alpha * exp(-gamma * d) ----
    #pragma unroll
    for (int mi = 0; mi < 2; mi++) {
        const int r0_ = mi * 16 + lr;
        const int r1_ = r0_ + 8;
        const float xq0 = xsq[r0_];
        const float xq1 = xsq[r1_];
        #pragma unroll
        for (int nj = 0; nj < 2; nj++) {
            const int c0 = n0 + nj * 8 + 2 * lc;
            const int c1 = c0 + 1;
            const float wq0 = wsq[c0], wq1 = wsq[c1];
            float d00 = xq0 + wq0 - 2.0f * acc[mi][nj][0];
            float d01 = xq0 + wq1 - 2.0f * acc[mi][nj][1];
            float d10 = xq1 + wq0 - 2.0f * acc[mi][nj][2];
            float d11 = xq1 + wq1 - 2.0f * acc[mi][nj][3];
            sit[r0_ * SROW + c0] = alp[c0] * __expf(-gam[c0] * d00);
            sit[r0_ * SROW + c1] = alp[c1] * __expf(-gam[c1] * d01);
            sit[r1_ * SROW + c0] = alp[c0] * __expf(-gam[c0] * d10);
            sit[r1_ * SROW + c1] = alp[c1] * __expf(-gam[c1] * d11);
        }
    }
    __syncthreads();

    // ---- scan: 4 threads per row (first 128 threads), linear recurrence ----
    if (tid < 4 * BM) {
        const int row = tid >> 2;
        const int g   = tid & 3;
        const float* srow = sit + row * SROW;

        float mx = -1e30f;
        #pragma unroll
        for (int j = 0; j < 8; j++) {
            float4 v = *(const float4*)&srow[g * 32 + j * 4];
            mx = fmaxf(mx, fmaxf(fmaxf(v.x, v.y), fmaxf(v.z, v.w)));
        }
        mx = fmaxf(mx, __shfl_xor_sync(0xffffffffu, mx, 1));
        mx = fmaxf(mx, __shfl_xor_sync(0xffffffffu, mx, 2));
        const float inv = 1.0f / (mx + 1e-4f);

        float s0_, s1_, s2_, o;
        {
            const float sp = srow[0] * inv;
            const float4 u4 = *(const float4*)&u_t[0 * UW + g * 4];
            o = 1.0f - sp;
            s0_ = fmaf(u4.x, sp, o);
            s1_ = fmaf(u4.y, sp, o);
            s2_ = fmaf(u4.z, sp, o);
        }

        #pragma unroll 8
        for (int p = 1; p < Pn; p++) {
            const float sp = srow[p] * inv;
            const float4 u4 = *(const float4*)&u_t[p * UW + g * 4];
            const float o2 = 1.0f - sp;
            const float oo2 = o * o2;
            const float add = oo2 + oo2;
            s0_ = fmaf(s0_, fmaf(u4.x, sp, o2), add);
            s1_ = fmaf(s1_, fmaf(u4.y, sp, o2), add);
            s2_ = fmaf(s2_, fmaf(u4.z, sp, o2), add);
            o = 3.0f * oo2;
            if ((p & 7) == 7) {   // periodic renormalization (pure rescale)
                float part = (g == 3) ? s0_ : (s0_ + s1_ + s2_);
                part += __shfl_xor_sync(0xffffffffu, part, 1);
                part += __shfl_xor_sync(0xffffffffu, part, 2);
                const float rr = __fdividef(1.0f, part - 9.0f * o);
                s0_ *= rr; s1_ *= rr; s2_ *= rr; o *= rr;
            }
        }

        float part = (g == 3) ? s0_ : (s0_ + s1_ + s2_);
        part += __shfl_xor_sync(0xffffffffu, part, 1);
        part += __shfl_xor_sync(0xffffffffu, part, 2);
        const float rr = __fdividef(1.0f, part - 9.0f * o);

        float* orow = out + (size_t)(row0 + row) * (Cn + 1);
        if (g < 3) {
            orow[3 * g + 0] = (s0_ - o) * rr;
            orow[3 * g + 1] = (s1_ - o) * rr;
            orow[3 * g + 2] = (s2_ - o) * rr;
        } else {
            orow[9]  = (s0_ - o) * rr;
            orow[10] = o * rr;
        }
    }
}

extern "C" void kernel_launch(void* const* d_in, const int* in_sizes, int n_in,
                              void* d_out, int out_size)
{
    const float* x    = (const float*)d_in[0];
    const float* w    = (const float*)d_in[1];
    const float* eta  = (const float*)d_in[2];
    const float* xi   = (const float*)d_in[3];
    const float* beta = (const float*)d_in[4];
    float* out = (float*)d_out;

    cudaFuncSetAttribute(ds_kernel, cudaFuncAttributeMaxDynamicSharedMemorySize,
                         SMEM_BYTES);

    ds_kernel<<<Bn / BM, NT, SMEM_BYTES>>>(x, w, eta, xi, beta, out);
}